// round 6
// baseline (speedup 1.0000x reference)
#include <cuda_runtime.h>

#define NELEM 16384
#define NBINS 16384
#define NT    1024
#define IT    16          // NELEM / NT
#define MARGIN_F 0.3f

#define BIN_LO    (-0.3125f)
#define BIN_SCALE (12483.047619047619f)   // 16384 / 1.3125

#define SMEM_BYTES (NBINS*4 + NBINS*4 + 32*8 + 32*4 + 32*8 + 32*4)

// Persistent scratch (zero-init at load; K2 re-zeros g_cnt/g_sum each run,
// K0 overwrites g_isI64 each run, K1 overwrites g_s each run).
__device__ unsigned g_isI64;
__device__ __align__(16) unsigned g_cnt[NBINS];
__device__ __align__(16) float    g_sum[NBINS];
__device__ __align__(16) float    g_s[NELEM];

__device__ __forceinline__ int bin_of(float v) {
    int b = (int)((v - BIN_LO) * BIN_SCALE);   // monotone nondecreasing
    return b < 0 ? 0 : (b > NBINS - 1 ? NBINS - 1 : b);
}

// ---------------------------------------------------------------------------
// K0: target-dtype detection. int64 storage <=> every odd 32-bit word among
// the first NELEM words is zero. Only reads words that are in-bounds under
// BOTH layouts. Plain (non-atomic) final store -> no reset needed.
// ---------------------------------------------------------------------------
__global__ void k_detect(const unsigned* __restrict__ w) {
    __shared__ unsigned sh[16];
    unsigned o = 0;
    for (int i = 2 * (int)threadIdx.x + 1; i < NELEM; i += 2 * (int)blockDim.x)
        o |= w[i];
    #pragma unroll
    for (int d = 16; d; d >>= 1) o |= __shfl_xor_sync(0xFFFFFFFFu, o, d);
    if ((threadIdx.x & 31) == 0) sh[threadIdx.x >> 5] = o;
    __syncthreads();
    if (threadIdx.x == 0) {
        unsigned r = 0;
        for (int k = 0; k < (int)(blockDim.x >> 5); ++k) r |= sh[k];
        g_isI64 = (r == 0u) ? 1u : 0u;
    }
}

// ---------------------------------------------------------------------------
// K1: full-chip sigmoid + per-bin {count, sum} histogram of negatives.
// ---------------------------------------------------------------------------
__global__ void k_prep(const float* __restrict__ x,
                       const unsigned* __restrict__ w, int n) {
    int i = blockIdx.x * blockDim.x + threadIdx.x;
    if (i >= n) return;
    float s = 1.0f / (1.0f + __expf(-x[i]));
    g_s[i] = s;
    unsigned lab = g_isI64 ? w[2 * i] : w[i];
    if (lab == 0u) {                      // negative
        int b = bin_of(s);
        atomicAdd(&g_cnt[b], 1u);
        atomicAdd(&g_sum[b], s);
    }
}

// ---------------------------------------------------------------------------
// K2: single CTA — fused scans of bin counts/sums, per-positive lookups,
// block reduction. Re-zeros the global histograms for the next replay.
// ---------------------------------------------------------------------------
__global__ __launch_bounds__(NT, 1) void k_main(const unsigned* __restrict__ w,
                                                float* __restrict__ out) {
    extern __shared__ unsigned char smraw[];
    unsigned* Cinc = (unsigned*)smraw;                        // [NBINS]
    float*    Sinc = (float*)(smraw + NBINS * 4);             // [NBINS]
    double*   aggD = (double*)(smraw + NBINS * 8);            // [32]
    unsigned* aggU = (unsigned*)(aggD + 32);                  // [32]
    double*   redD = (double*)(aggU + 32);                    // [32]
    unsigned* redU = (unsigned*)(redD + 32);                  // [32]

    const int tid  = threadIdx.x;
    const int lane = tid & 31;
    const int wid  = tid >> 5;

    // ---- Phase A: load bin {cnt,sum} vectorized, zero globals, fused scan ----
    unsigned c[IT];
    float    v[IT];
    {
        const uint4*  c4 = (const uint4*)g_cnt;
        const float4* s4 = (const float4*)g_sum;
        uint4*  cw4 = (uint4*)g_cnt;
        float4* sw4 = (float4*)g_sum;
        const uint4  uz = make_uint4(0u, 0u, 0u, 0u);
        const float4 fz = make_float4(0.f, 0.f, 0.f, 0.f);
        #pragma unroll
        for (int q = 0; q < 4; ++q) {
            uint4 u = c4[tid * 4 + q];
            c[4*q+0] = u.x; c[4*q+1] = u.y; c[4*q+2] = u.z; c[4*q+3] = u.w;
            cw4[tid * 4 + q] = uz;
            float4 f = s4[tid * 4 + q];
            v[4*q+0] = f.x; v[4*q+1] = f.y; v[4*q+2] = f.z; v[4*q+3] = f.w;
            sw4[tid * 4 + q] = fz;
        }
    }
    unsigned crun = 0; float vrun = 0.f;
    #pragma unroll
    for (int k = 0; k < IT; ++k) {
        crun += c[k]; c[k] = crun;
        vrun += v[k]; v[k] = vrun;
    }
    // warp-inclusive scan of per-thread totals (count: u32, sum: double carry)
    unsigned cw = crun;
    double   vw = (double)vrun;
    #pragma unroll
    for (int d = 1; d < 32; d <<= 1) {
        unsigned cs = __shfl_up_sync(0xFFFFFFFFu, cw, d);
        double   vs = __shfl_up_sync(0xFFFFFFFFu, vw, d);
        if (lane >= d) { cw += cs; vw += vs; }
    }
    if (lane == 31) { aggU[wid] = cw; aggD[wid] = vw; }
    __syncthreads();
    if (wid == 0) {                 // scan the 32 warp aggregates
        unsigned a = aggU[lane];
        double   b = aggD[lane];
        #pragma unroll
        for (int d = 1; d < 32; d <<= 1) {
            unsigned as = __shfl_up_sync(0xFFFFFFFFu, a, d);
            double   bs = __shfl_up_sync(0xFFFFFFFFu, b, d);
            if (lane >= d) { a += as; b += bs; }
        }
        aggU[lane] = a; aggD[lane] = b;
    }
    __syncthreads();
    const unsigned warpOfsC = wid ? aggU[wid - 1] : 0u;
    const double   warpOfsS = wid ? aggD[wid - 1] : 0.0;
    const unsigned nneg   = aggU[31];
    const double   totalS = aggD[31];
    const unsigned cofs = warpOfsC + cw - crun;          // thread-exclusive
    const double   sofs = warpOfsS + vw - (double)vrun;
    {
        uint4*  C4 = (uint4*)Cinc;
        float4* S4 = (float4*)Sinc;
        #pragma unroll
        for (int q = 0; q < 4; ++q) {
            uint4 u;
            u.x = cofs + c[4*q+0]; u.y = cofs + c[4*q+1];
            u.z = cofs + c[4*q+2]; u.w = cofs + c[4*q+3];
            C4[tid * 4 + q] = u;
            float4 f;
            f.x = (float)(sofs + v[4*q+0]); f.y = (float)(sofs + v[4*q+1]);
            f.z = (float)(sofs + v[4*q+2]); f.w = (float)(sofs + v[4*q+3]);
            S4[tid * 4 + q] = f;
        }
    }
    __syncthreads();

    // ---- Phase B: per-positive lookups ----
    double   acc = 0.0;
    unsigned np  = 0u;
    const unsigned isI64 = g_isI64;
    {
        const float4* gs4 = (const float4*)g_s;
        const uint4*  w4  = (const uint4*)w;
        #pragma unroll
        for (int q = 0; q < 4; ++q) {
            float4 f = gs4[tid * 4 + q];
            unsigned lab[4];
            if (isI64) {
                uint4 a = w4[(tid * 4 + q) * 2];
                uint4 b = w4[(tid * 4 + q) * 2 + 1];
                lab[0] = a.x; lab[1] = a.z; lab[2] = b.x; lab[3] = b.z;
            } else {
                uint4 a = w4[tid * 4 + q];
                lab[0] = a.x; lab[1] = a.y; lab[2] = a.z; lab[3] = a.w;
            }
            float sv[4] = {f.x, f.y, f.z, f.w};
            #pragma unroll
            for (int k = 0; k < 4; ++k) {
                if (lab[k] != 0u) {                      // positive
                    ++np;
                    float t = sv[k] - MARGIN_F;
                    int b = bin_of(t);
                    unsigned cb = b ? Cinc[b - 1] : 0u;
                    float    sb = b ? Sinc[b - 1] : 0.f;
                    acc += (totalS - (double)sb)
                         - (double)t * (double)(nneg - cb);
                }
            }
        }
    }

    // ---- Phase C: block reduction ----
    #pragma unroll
    for (int d = 16; d; d >>= 1) {
        acc += __shfl_xor_sync(0xFFFFFFFFu, acc, d);
        np  += __shfl_xor_sync(0xFFFFFFFFu, np,  d);
    }
    if (lane == 0) { redD[wid] = acc; redU[wid] = np; }
    __syncthreads();
    if (tid == 0) {
        double   A = 0.0;
        unsigned P = 0u;
        #pragma unroll
        for (int k = 0; k < 32; ++k) { A += redD[k]; P += redU[k]; }
        out[0] = (float)(A / ((double)P * (double)nneg));
    }
}

// ---------------------------------------------------------------------------
extern "C" void kernel_launch(void* const* d_in, const int* in_sizes, int n_in,
                              void* d_out, int out_size) {
    const float*    x   = (const float*)d_in[0];
    const unsigned* w   = (const unsigned*)d_in[1];   // targets, dtype-agnostic view
    float*          out = (float*)d_out;
    int n = in_sizes[0];

    cudaFuncSetAttribute(k_main, cudaFuncAttributeMaxDynamicSharedMemorySize,
                         SMEM_BYTES);

    k_detect<<<1, 512>>>(w);
    k_prep<<<(n + 255) / 256, 256>>>(x, w, n);
    k_main<<<1, NT, SMEM_BYTES>>>(w, out);
}

// round 8
// speedup vs baseline: 4.2989x; 4.2989x over previous
#include <cuda_runtime.h>

#define NBINS   2048
#define CTA_THR 256
#define BPT     8               // NBINS / CTA_THR bins per thread in phase 2
#define MARGIN_F 0.3f
#define BIN_LO   (-0.3125f)
#define BIN_SCALE 1560.3809523809523f   /* NBINS / 1.3125 */

// Persistent scratch: zero-initialized at load; phase 2 re-zeros everything it
// consumed, so every graph replay starts from the same state.
__device__ __align__(16) unsigned g_negCnt[NBINS];
__device__ __align__(16) float    g_negSum[NBINS];
__device__ __align__(16) unsigned g_posCnt[NBINS];
__device__ __align__(16) float    g_posT[NBINS];
__device__ unsigned g_done;

__device__ __forceinline__ int bin_of(float v) {
    int b = (int)((v - BIN_LO) * BIN_SCALE);   // monotone nondecreasing
    return b < 0 ? 0 : (b > NBINS - 1 ? NBINS - 1 : b);
}

// ---------------------------------------------------------------------------
// Single fused kernel.
// Phase 1 (all CTAs): per-CTA target-dtype detect, sigmoid, histogram REDs.
// Phase 2 (last CTA): scan + bin-space contraction + scalar output + reset.
// ---------------------------------------------------------------------------
__global__ __launch_bounds__(CTA_THR, 1)
void k_all(const float* __restrict__ x, const unsigned* __restrict__ w,
           float* __restrict__ out, int n) {
    const int tid = threadIdx.x;
    const int cta = blockIdx.x;
    const int i   = cta * CTA_THR + tid;

    // ---- dtype detect: int64 storage <=> odd 32-bit words are all zero.
    // Each CTA checks 128 odd words with index < n (in-bounds either layout).
    unsigned oddw = 0;
    if (tid < 128) oddw = w[2 * (cta * 128 + tid) + 1];
    const int isI64 = (__syncthreads_or((int)(oddw != 0u)) == 0);

    // ---- phase 1: sigmoid + histograms (spread-address REDs, no returns)
    if (i < n) {
        float s = 1.0f / (1.0f + __expf(-x[i]));
        unsigned lab = isI64 ? w[2 * i] : w[i];
        if (lab == 0u) {                       // negative
            int b = bin_of(s);
            atomicAdd(&g_negCnt[b], 1u);
            atomicAdd(&g_negSum[b], s);
        } else {                               // positive: histogram threshold
            float t = s - MARGIN_F;
            int b = bin_of(t);
            atomicAdd(&g_posCnt[b], 1u);
            atomicAdd(&g_posT[b], t);
        }
    }

    // ---- last-CTA handoff (threadFenceReduction pattern)
    __shared__ unsigned sh_ticket;
    __threadfence();
    __syncthreads();
    if (tid == 0) sh_ticket = atomicAdd(&g_done, 1u);
    __syncthreads();
    if (sh_ticket != (unsigned)(gridDim.x - 1)) return;

    // =======================================================================
    // Phase 2: one CTA (256 threads), 8 bins per thread.
    // =======================================================================
    __shared__ double   aggS[8];      // per-warp sum aggregates (double carry)
    __shared__ unsigned aggC[8];      // per-warp count aggregates
    __shared__ double   ofsS[8];      // exclusive warp offsets
    __shared__ unsigned ofsC[8];
    __shared__ double   sh_totalS;
    __shared__ unsigned sh_nneg;
    __shared__ double   redD[8];
    __shared__ unsigned redU[8];

    const int lane = tid & 31;
    const int wid  = tid >> 5;

    unsigned c[BPT], pc[BPT];
    float    v[BPT], pt[BPT];
    {   // vectorized load of all four histograms + re-zero for next replay
        const uint4*  C4 = (const uint4*)g_negCnt;
        const float4* S4 = (const float4*)g_negSum;
        const uint4*  P4 = (const uint4*)g_posCnt;
        const float4* T4 = (const float4*)g_posT;
        uint4*  Cw = (uint4*)g_negCnt;   float4* Sw = (float4*)g_negSum;
        uint4*  Pw = (uint4*)g_posCnt;   float4* Tw = (float4*)g_posT;
        const uint4  uz = make_uint4(0u, 0u, 0u, 0u);
        const float4 fz = make_float4(0.f, 0.f, 0.f, 0.f);
        #pragma unroll
        for (int q = 0; q < BPT / 4; ++q) {
            uint4 a = C4[tid * 2 + q];
            c[4*q+0]=a.x; c[4*q+1]=a.y; c[4*q+2]=a.z; c[4*q+3]=a.w;
            Cw[tid * 2 + q] = uz;
            float4 f = S4[tid * 2 + q];
            v[4*q+0]=f.x; v[4*q+1]=f.y; v[4*q+2]=f.z; v[4*q+3]=f.w;
            Sw[tid * 2 + q] = fz;
            uint4 p = P4[tid * 2 + q];
            pc[4*q+0]=p.x; pc[4*q+1]=p.y; pc[4*q+2]=p.z; pc[4*q+3]=p.w;
            Pw[tid * 2 + q] = uz;
            float4 g = T4[tid * 2 + q];
            pt[4*q+0]=g.x; pt[4*q+1]=g.y; pt[4*q+2]=g.z; pt[4*q+3]=g.w;
            Tw[tid * 2 + q] = fz;
        }
    }
    if (tid == 0) g_done = 0u;   // reset ticket for next replay

    // local inclusive scans over this thread's 8 consecutive bins
    unsigned crun = 0; float vrun = 0.f;
    #pragma unroll
    for (int k = 0; k < BPT; ++k) {
        crun += c[k]; c[k] = crun;
        vrun += v[k]; v[k] = vrun;
    }
    // warp-inclusive scan of per-thread totals
    unsigned cw = crun;
    double   sw = (double)vrun;
    #pragma unroll
    for (int d = 1; d < 32; d <<= 1) {
        unsigned cs = __shfl_up_sync(0xFFFFFFFFu, cw, d);
        double   ss = __shfl_up_sync(0xFFFFFFFFu, sw, d);
        if (lane >= d) { cw += cs; sw += ss; }
    }
    if (lane == 31) { aggC[wid] = cw; aggS[wid] = sw; }
    __syncthreads();
    if (tid == 0) {                       // serial scan of 8 warp aggregates
        unsigned rc = 0; double rs = 0.0;
        #pragma unroll
        for (int k = 0; k < 8; ++k) {
            ofsC[k] = rc; ofsS[k] = rs;
            rc += aggC[k]; rs += aggS[k];
        }
        sh_nneg = rc; sh_totalS = rs;
    }
    __syncthreads();
    const unsigned nneg   = sh_nneg;
    const double   totalS = sh_totalS;
    const unsigned cofs = ofsC[wid] + (cw - crun);     // thread-exclusive
    const double   sofs = ofsS[wid] + (sw - (double)vrun);

    // bin-space contraction
    double   acc = 0.0;
    unsigned np  = 0u;
    #pragma unroll
    for (int k = 0; k < BPT; ++k) {
        unsigned Cinc = cofs + c[k];                   // inclusive count prefix
        double   Sinc = sofs + (double)v[k];           // inclusive sum prefix
        acc += (double)pc[k] * (totalS - Sinc)
             - (double)pt[k] * (double)(nneg - Cinc);
        np  += pc[k];
    }

    // block reduction
    #pragma unroll
    for (int d = 16; d; d >>= 1) {
        acc += __shfl_xor_sync(0xFFFFFFFFu, acc, d);
        np  += __shfl_xor_sync(0xFFFFFFFFu, np,  d);
    }
    if (lane == 0) { redD[wid] = acc; redU[wid] = np; }
    __syncthreads();
    if (tid == 0) {
        double   A = 0.0;
        unsigned P = 0u;
        #pragma unroll
        for (int k = 0; k < 8; ++k) { A += redD[k]; P += redU[k]; }
        out[0] = (float)(A / ((double)P * (double)nneg));
    }
}

// ---------------------------------------------------------------------------
extern "C" void kernel_launch(void* const* d_in, const int* in_sizes, int n_in,
                              void* d_out, int out_size) {
    const float*    x   = (const float*)d_in[0];
    const unsigned* w   = (const unsigned*)d_in[1];  // targets, dtype-agnostic
    float*          out = (float*)d_out;
    int n = in_sizes[0];

    k_all<<<(n + CTA_THR - 1) / CTA_THR, CTA_THR>>>(x, w, out, n);
}